// round 15
// baseline (speedup 1.0000x reference)
#include <cuda_runtime.h>
#include <cuda_fp16.h>
#include <cstdint>

// ---------------------------------------------------------------------------
// TUPE multihead attention — plain fp16 HMMA (fp32 accumulate) everywhere.
//  Projections: 128x128x64 tile (sw128), cp.async double-buffered, qkv+PE
//  merged into one launch. Flash: 2 CTAs/SM, KV double-buffered, f32 PE_r
//  bias read directly (single-buffered cp.async, no pre-pack kernel).
// ---------------------------------------------------------------------------

static constexpr int BB  = 4;
static constexpr int HH  = 8;
static constexpr int SQ  = 2048;
static constexpr int EMB = 512;
static constexpr int HD  = 64;
static constexpr float LOG2E = 1.4426950408889634f;
static constexpr float QK_SCALE_L2E = 0.0883883476483184f * LOG2E;

// ------------------------------ scratch ------------------------------------
__device__ __align__(16) unsigned short g_x2  [(size_t)BB * SQ * EMB];
__device__ __align__(16) unsigned short g_PE2 [(size_t)BB * SQ * EMB];
__device__ __align__(16) unsigned short g_W2  [(size_t)3 * EMB * EMB];
__device__ __align__(16) unsigned short g_U2  [(size_t)2 * EMB * EMB];
__device__ __align__(16) unsigned short g_Wo2 [(size_t)EMB * EMB];
__device__ __align__(16) unsigned short g_Qcat[(size_t)BB * HH * SQ * 128]; // fp16 (x s*log2e)
__device__ __align__(16) unsigned short g_KH[(size_t)BB * HH * SQ * 128];   // K image sw64
__device__ __align__(16) unsigned short g_VH[(size_t)BB * HH * HD * SQ];    // V image sw64
__device__ __align__(16) unsigned short g_vals[(size_t)BB * SQ * EMB];

// ------------------------------ helpers ------------------------------------
__device__ __forceinline__ unsigned smem_u32(const void* p) {
    unsigned a;
    asm("{ .reg .u64 t; cvta.to.shared.u64 t, %1; cvt.u32.u64 %0, t; }" : "=r"(a) : "l"(p));
    return a;
}
__device__ __forceinline__ unsigned h2u(__half2 h) {
    return *reinterpret_cast<unsigned*>(&h);
}
__device__ __forceinline__ float ex2f(float x) {
    float r;
    asm("ex2.approx.f32 %0, %1;" : "=f"(r) : "f"(x));
    return r;
}

// merged pack: five f32 inputs -> fp16, segment dispatch by index
__global__ void __launch_bounds__(256)
pack_all_kernel(const float4* __restrict__ x,  const float4* __restrict__ pe,
                const float4* __restrict__ w,  const float4* __restrict__ u,
                const float4* __restrict__ wo,
                uint2* __restrict__ ox, uint2* __restrict__ ope,
                uint2* __restrict__ ow, uint2* __restrict__ ou,
                uint2* __restrict__ owo)
{
    const int N0 = 1048576, N1 = 2097152, N2 = 2293760, N3 = 2424832, N4 = 2490368;
    int i = blockIdx.x * 256 + threadIdx.x;
    if (i >= N4) return;
    const float4* src; uint2* dst; int j;
    if (i < N0)      { src = x;  dst = ox;  j = i; }
    else if (i < N1) { src = pe; dst = ope; j = i - N0; }
    else if (i < N2) { src = w;  dst = ow;  j = i - N1; }
    else if (i < N3) { src = u;  dst = ou;  j = i - N2; }
    else             { src = wo; dst = owo; j = i - N3; }
    float4 v = src[j];
    dst[j] = make_uint2(h2u(__floats2half2_rn(v.x, v.y)),
                        h2u(__floats2half2_rn(v.z, v.w)));
}

#define LDSM4(r0, r1, r2, r3, a)                                              \
    asm volatile("ldmatrix.sync.aligned.m8n8.x4.shared.b16 {%0,%1,%2,%3}, [%4];" \
                 : "=r"(r0), "=r"(r1), "=r"(r2), "=r"(r3) : "r"(a))

#define MMA16816H(c, a, b0, b1)                                               \
    asm volatile("mma.sync.aligned.m16n8k16.row.col.f32.f16.f16.f32 "         \
                 "{%0,%1,%2,%3}, {%4,%5,%6,%7}, {%8,%9}, {%0,%1,%2,%3};"      \
                 : "+f"((c)[0]), "+f"((c)[1]), "+f"((c)[2]), "+f"((c)[3])     \
                 : "r"((a)[0]), "r"((a)[1]), "r"((a)[2]), "r"((a)[3]),        \
                   "r"(b0), "r"(b1))

#define CP_ASYNC16(dst, src) \
    asm volatile("cp.async.cg.shared.global [%0], [%1], 16;" :: "r"(dst), "l"(src))
#define CP_COMMIT() asm volatile("cp.async.commit_group;" ::: "memory")
#define CP_WAIT0()  asm volatile("cp.async.wait_group 0;" ::: "memory")
#define CP_WAIT1()  asm volatile("cp.async.wait_group 1;" ::: "memory")

__device__ __forceinline__ unsigned sw64(unsigned off)   { return off ^ ((off >> 3) & 0x30); }
__device__ __forceinline__ unsigned sw128(unsigned off)  { return off ^ ((off >> 3) & 0x70); }

// ------------------------------ GEMM core (projections / out) --------------
// C[128 x 128]; A fp16 [M,K]; B fp16 [N,K]; K mult of 64. Warp tile 32x64.
template <typename Epi>
__device__ __forceinline__ void gemm_core(
    const unsigned short* __restrict__ Ab, const unsigned short* __restrict__ Bb,
    int K, int lda, int ldb, int bx, int by, int bz, Epi epi, char* smem)
{
    constexpr int SBOF = 16384, STAGE = 32768;
    const int tid = threadIdx.x;
    const int l   = tid & 31;
    const int w   = tid >> 5;
    const int m0  = (w & 3) * 32;
    const int n0  = (w >> 2) * 64;
    const unsigned sbase = smem_u32(smem);

    float acc[2][8][4];
#pragma unroll
    for (int i = 0; i < 2; i++)
#pragma unroll
        for (int j = 0; j < 8; j++)
#pragma unroll
            for (int k = 0; k < 4; k++) acc[i][j][k] = 0.0f;

    const int arow = (l & 7) + ((l >> 3) & 1) * 8;
    const int akp  = ((l >> 4) & 1) * 16;
    const int brow = (l & 7) + ((l >> 4) & 1) * 8;
    const int bkp  = ((l >> 3) & 1) * 16;

    const int nChunks = K >> 6;

    auto prefetch = [&](int c) {
        const unsigned sb = sbase + (c & 1) * STAGE;
#pragma unroll
        for (int it = 0; it < 4; it++) {
            int idx = tid + it * 256;
            int r = idx >> 3, q = idx & 7;
            CP_ASYNC16(sb + sw128(r * 128 + q * 16), Ab + (long)r * lda + c * 64 + q * 8);
        }
#pragma unroll
        for (int it = 0; it < 4; it++) {
            int idx = tid + it * 256;
            int r = idx >> 3, q = idx & 7;
            CP_ASYNC16(sb + SBOF + sw128(r * 128 + q * 16), Bb + (long)r * ldb + c * 64 + q * 8);
        }
    };

    prefetch(0);
    CP_COMMIT();

    for (int c = 0; c < nChunks; c++) {
        if (c + 1 < nChunks) {
            prefetch(c + 1);
            CP_COMMIT();
            CP_WAIT1();
        } else {
            CP_WAIT0();
        }
        __syncthreads();

        const unsigned stage = sbase + (c & 1) * STAGE;
#pragma unroll
        for (int ks = 0; ks < 4; ks++) {
            unsigned aH[2][4], bH[4][4];
#pragma unroll
            for (int i = 0; i < 2; i++) {
                unsigned off = (m0 + i * 16 + arow) * 128 + ks * 32 + akp;
                LDSM4(aH[i][0], aH[i][1], aH[i][2], aH[i][3], stage + sw128(off));
            }
#pragma unroll
            for (int p = 0; p < 4; p++) {
                unsigned off = (n0 + p * 16 + brow) * 128 + ks * 32 + bkp;
                LDSM4(bH[p][0], bH[p][1], bH[p][2], bH[p][3], stage + SBOF + sw128(off));
            }
#pragma unroll
            for (int i = 0; i < 2; i++)
#pragma unroll
                for (int j = 0; j < 8; j++) {
                    const int p = j >> 1, h = (j & 1) * 2;
                    MMA16816H(acc[i][j], aH[i], bH[p][h], bH[p][h + 1]);
                }
        }
        __syncthreads();
    }

    float* C = reinterpret_cast<float*>(smem);
#pragma unroll
    for (int i = 0; i < 2; i++)
#pragma unroll
        for (int j = 0; j < 8; j++) {
            int r0  = m0 + i * 16 + (l >> 2);
            int col = n0 + j * 8 + (l & 3) * 2;
            *reinterpret_cast<float2*>(C + r0 * 132 + col)       = make_float2(acc[i][j][0], acc[i][j][1]);
            *reinterpret_cast<float2*>(C + (r0 + 8) * 132 + col) = make_float2(acc[i][j][2], acc[i][j][3]);
        }
    __syncthreads();

    {
        int r = tid >> 1, seg = (tid & 1) << 6;
        int m  = by * 128 + r;
        int nb = bx * 128 + seg;
        const float* Crow = C + r * 132 + seg;
#pragma unroll
        for (int i = 0; i < 16; i++) {
            float4 v = *reinterpret_cast<const float4*>(Crow + i * 4);
            epi(bz, m, nb + i * 4, v);
        }
    }
}

// ------------------------------ epilogues ----------------------------------
struct EpiQKV {   // m in [0,8192), n in [0,1536)
    __device__ void operator()(int, int m, int n, float4 v) const {
        int b = m >> 11, s = m & (SQ - 1);
        int h = n / 192, r = n - h * 192;
        int bh = b * HH + h;
        if (r < HD) {
            long row = ((long)bh * SQ + s);
            *reinterpret_cast<uint2*>(&g_Qcat[row * 128 + r]) =
                make_uint2(h2u(__floats2half2_rn(v.x * QK_SCALE_L2E, v.y * QK_SCALE_L2E)),
                           h2u(__floats2half2_rn(v.z * QK_SCALE_L2E, v.w * QK_SCALE_L2E)));
        } else if (r < 2 * HD) {
            int d0 = r - HD;
            int ck = s >> 6, rr = s & 63;
            long base = ((long)bh * 32 + ck) * 16384;
            unsigned off = (unsigned)((d0 >> 5) * 4096) + sw64(rr * 64 + (d0 & 31) * 2);
            *reinterpret_cast<uint2*>(reinterpret_cast<char*>(g_KH) + base + off) =
                make_uint2(h2u(__floats2half2_rn(v.x, v.y)),
                           h2u(__floats2half2_rn(v.z, v.w)));
        } else {
            int d = r - 2 * HD;
            int ck = s >> 6, kc = s & 63;
            long base = ((long)bh * 32 + ck) * 8192 + (kc >> 5) * 4096;
            int kb = (kc & 31) * 2;
#pragma unroll
            for (int i = 0; i < 4; i++) {
                float val = (&v.x)[i];
                unsigned off2 = sw64((d + i) * 64 + kb);
                *reinterpret_cast<__half*>(reinterpret_cast<char*>(g_VH) + base + off2) =
                    __float2half(val);
            }
        }
    }
};
struct EpiPE {    // n in [0,1024)
    __device__ void operator()(int, int m, int n, float4 v) const {
        int b = m >> 11, s = m & (SQ - 1);
        int h = n >> 7, r = n & 127;
        int bh = b * HH + h;
        if (r < HD) {
            long row = ((long)bh * SQ + s);
            *reinterpret_cast<uint2*>(&g_Qcat[row * 128 + HD + r]) =
                make_uint2(h2u(__floats2half2_rn(v.x * QK_SCALE_L2E, v.y * QK_SCALE_L2E)),
                           h2u(__floats2half2_rn(v.z * QK_SCALE_L2E, v.w * QK_SCALE_L2E)));
        } else {
            int d0 = r;
            int ck = s >> 6, rr = s & 63;
            long base = ((long)bh * 32 + ck) * 16384;
            unsigned off = (unsigned)((d0 >> 5) * 4096) + sw64(rr * 64 + (d0 & 31) * 2);
            *reinterpret_cast<uint2*>(reinterpret_cast<char*>(g_KH) + base + off) =
                make_uint2(h2u(__floats2half2_rn(v.x, v.y)),
                           h2u(__floats2half2_rn(v.z, v.w)));
        }
    }
};
struct EpiOut {
    float* out;
    __device__ void operator()(int, int m, int n, float4 v) const {
        *reinterpret_cast<float4*>(&out[(long)m * EMB + n]) = v;
    }
};

// ------------------------------ merged projection kernel -------------------
__global__ void __launch_bounds__(256, 2)
proj_kernel(const unsigned short* __restrict__ x2, const unsigned short* __restrict__ w2,
            const unsigned short* __restrict__ pe2, const unsigned short* __restrict__ u2)
{
    extern __shared__ __align__(1024) char smem[];
    const int bx = blockIdx.x, by = blockIdx.y;
    if (bx < 12) {
        gemm_core(x2 + (long)by * 128 * EMB, w2 + (long)bx * 128 * EMB,
                  EMB, EMB, EMB, bx, by, 0, EpiQKV{}, smem);
    } else {
        gemm_core(pe2 + (long)by * 128 * EMB, u2 + (long)(bx - 12) * 128 * EMB,
                  EMB, EMB, EMB, bx - 12, by, 0, EpiPE{}, smem);
    }
}

__global__ void __launch_bounds__(256, 2)
outproj_kernel(const unsigned short* __restrict__ vals, const unsigned short* __restrict__ wo2,
               float* __restrict__ out)
{
    extern __shared__ __align__(1024) char smem[];
    gemm_core(vals + (long)blockIdx.y * 128 * EMB, wo2 + (long)blockIdx.x * 128 * EMB,
              EMB, EMB, EMB, blockIdx.x, blockIdx.y, 0, EpiOut{out}, smem);
}

// ------------------------------ flash attention ----------------------------
// One CTA = 128 q-rows of one (b,h). 8 warps x 16 q-rows. KV chunk = 64 keys.
// 2 CTAs/SM: smem 84KB = KV x2 @0 + f32 bias single buffer @49152 (stride 272).
// Bias(ck+1) cp.async issued after bias-add(ck) in its own commit group.
__global__ void __launch_bounds__(256, 2)
flash_attn(const unsigned short* __restrict__ Qc, const char* __restrict__ KH,
           const char* __restrict__ VH, const float* __restrict__ PE_r,
           unsigned short* __restrict__ vals)
{
    extern __shared__ __align__(1024) char smem[];
    constexpr int KVBUF = 24576;     // KH 16K | VH 8K
    constexpr int SBIAS = 49152, BIAS_STRIDE = 272;   // 64 f32 + 16B pad per row
    constexpr int NCHUNK = SQ / 64;  // 32

    const int tid = threadIdx.x;
    const int l = tid & 31;
    const int w = tid >> 5;
    const int g = l >> 2;
    const int t = l & 3;
    const int bh = blockIdx.y;
    const int q0 = blockIdx.x * 128;
    const int qw = q0 + w * 16;
    const unsigned sbase = smem_u32(smem);

    const unsigned short* Qb = Qc + ((long)bh * SQ + qw) * 128;
    const char* KHb = KH + (long)bh * 32 * 16384;
    const char* VHb = VH + (long)bh * 32 * 8192;
    const float* Pb = PE_r + ((long)(bh & 7) * SQ + q0) * SQ;

    unsigned qH[8][4];
#pragma unroll
    for (int kc = 0; kc < 8; kc++) {
        qH[kc][0] = *reinterpret_cast<const unsigned*>(Qb + (long)g * 128 + kc * 16 + 2 * t);
        qH[kc][1] = *reinterpret_cast<const unsigned*>(Qb + (long)(g + 8) * 128 + kc * 16 + 2 * t);
        qH[kc][2] = *reinterpret_cast<const unsigned*>(Qb + (long)g * 128 + kc * 16 + 8 + 2 * t);
        qH[kc][3] = *reinterpret_cast<const unsigned*>(Qb + (long)(g + 8) * 128 + kc * 16 + 8 + 2 * t);
    }

    float oacc[8][4];
#pragma unroll
    for (int j = 0; j < 8; j++)
#pragma unroll
        for (int k = 0; k < 4; k++) oacc[j][k] = 0.0f;
    float m0r = -1e30f, m1r = -1e30f, l0r = 0.0f, l1r = 0.0f;

    const int brow = (l & 7) + ((l >> 4) & 1) * 8;
    const int bkp  = ((l >> 3) & 1) * 16;

    auto prefetch_kv = [&](int ck) {
        const unsigned sb = sbase + (ck & 1) * KVBUF;
        const char* kh = KHb + (long)ck * 16384;
        const char* vh = VHb + (long)ck * 8192;
#pragma unroll
        for (int it = 0; it < 4; it++) {
            int o = (tid + it * 256) * 16;
            CP_ASYNC16(sb + o, kh + o);
        }
#pragma unroll
        for (int it = 0; it < 2; it++) {
            int o = (tid + it * 256) * 16;
            CP_ASYNC16(sb + 16384 + o, vh + o);
        }
    };
    // f32 bias tile: 128 rows x 64 f32 (256B) per chunk; single buffer
    auto prefetch_bias = [&](int ck) {
        const unsigned bb = sbase + SBIAS;
#pragma unroll
        for (int it = 0; it < 8; it++) {
            int idx = tid + it * 256;
            int r = idx >> 4, c = idx & 15;
            CP_ASYNC16(bb + r * BIAS_STRIDE + c * 16,
                       Pb + (long)r * SQ + ck * 64 + c * 4);
        }
    };

    prefetch_kv(0);
    prefetch_bias(0);
    CP_COMMIT();

    for (int ck = 0; ck < NCHUNK; ck++) {
        // top: commit KV(ck+1); need KV(ck)+bias(ck) resident (committed earlier)
        if (ck + 1 < NCHUNK) {
            prefetch_kv(ck + 1);
            CP_COMMIT();
            CP_WAIT1();
        } else {
            CP_WAIT0();
        }
        __syncthreads();

        const unsigned kvb = sbase + (ck & 1) * KVBUF;

        // ---- S = qh * kh (log2-domain scores) ----
        float sacc[8][4];
#pragma unroll
        for (int j = 0; j < 8; j++)
#pragma unroll
            for (int k = 0; k < 4; k++) sacc[j][k] = 0.0f;

#pragma unroll
        for (int kc = 0; kc < 8; kc++) {
            unsigned bH[4][4];
            const unsigned slab = kvb + (kc >> 1) * 4096;
            const unsigned koff = (kc & 1) * 32 + bkp;
#pragma unroll
            for (int p = 0; p < 4; p++) {
                unsigned sw = sw64((p * 16 + brow) * 64 + koff);
                LDSM4(bH[p][0], bH[p][1], bH[p][2], bH[p][3], slab + sw);
            }
#pragma unroll
            for (int j = 0; j < 8; j++) {
                const int p = j >> 1, h = (j & 1) * 2;
                MMA16816H(sacc[j], qH[kc], bH[p][h], bH[p][h + 1]);
            }
        }

        // ---- bias add (f32 smem, x log2e at add) ----
        {
            const char* bb = smem + SBIAS;
            const int r0 = w * 16 + g, r1 = r0 + 8;
#pragma unroll
            for (int j = 0; j < 8; j++) {
                float2 b0 = *reinterpret_cast<const float2*>(bb + r0 * BIAS_STRIDE + (j * 8 + 2 * t) * 4);
                float2 b1 = *reinterpret_cast<const float2*>(bb + r1 * BIAS_STRIDE + (j * 8 + 2 * t) * 4);
                sacc[j][0] = fmaf(b0.x, LOG2E, sacc[j][0]);
                sacc[j][1] = fmaf(b0.y, LOG2E, sacc[j][1]);
                sacc[j][2] = fmaf(b1.x, LOG2E, sacc[j][2]);
                sacc[j][3] = fmaf(b1.y, LOG2E, sacc[j][3]);
            }
        }
        __syncthreads();   // all warps done reading bias buffer
        if (ck + 1 < NCHUNK) {
            prefetch_bias(ck + 1);   // own group; waited at next top
            CP_COMMIT();
        }

        // ---- online softmax (log2 domain) ----
        float mx0 = -1e30f, mx1 = -1e30f;
#pragma unroll
        for (int j = 0; j < 8; j++) {
            mx0 = fmaxf(mx0, fmaxf(sacc[j][0], sacc[j][1]));
            mx1 = fmaxf(mx1, fmaxf(sacc[j][2], sacc[j][3]));
        }
        mx0 = fmaxf(mx0, __shfl_xor_sync(0xffffffffu, mx0, 1));
        mx0 = fmaxf(mx0, __shfl_xor_sync(0xffffffffu, mx0, 2));
        mx1 = fmaxf(mx1, __shfl_xor_sync(0xffffffffu, mx1, 1));
        mx1 = fmaxf(mx1, __shfl_xor_sync(0xffffffffu, mx1, 2));

        const float mn0 = fmaxf(m0r, mx0), mn1 = fmaxf(m1r, mx1);
        const float cor0 = ex2f(m0r - mn0), cor1 = ex2f(m1r - mn1);
        m0r = mn0; m1r = mn1;

        float sum0 = 0.0f, sum1 = 0.0f;
#pragma unroll
        for (int j = 0; j < 8; j++) {
            sacc[j][0] = ex2f(sacc[j][0] - mn0);
            sacc[j][1] = ex2f(sacc[j][1] - mn0);
            sacc[j][2] = ex2f(sacc[j][2] - mn1);
            sacc[j][3] = ex2f(sacc[j][3] - mn1);
            sum0 += sacc[j][0] + sacc[j][1];
            sum1 += sacc[j][2] + sacc[j][3];
        }
        sum0 += __shfl_xor_sync(0xffffffffu, sum0, 1);
        sum0 += __shfl_xor_sync(0xffffffffu, sum0, 2);
        sum1 += __shfl_xor_sync(0xffffffffu, sum1, 1);
        sum1 += __shfl_xor_sync(0xffffffffu, sum1, 2);
        l0r = l0r * cor0 + sum0;
        l1r = l1r * cor1 + sum1;

#pragma unroll
        for (int j = 0; j < 8; j++) {
            oacc[j][0] *= cor0; oacc[j][1] *= cor0;
            oacc[j][2] *= cor1; oacc[j][3] *= cor1;
        }

        // ---- PV: oacc += p * vh ----
#pragma unroll
        for (int kk = 0; kk < 4; kk++) {
            unsigned pH[4];
            pH[0] = h2u(__floats2half2_rn(sacc[2 * kk][0],     sacc[2 * kk][1]));
            pH[1] = h2u(__floats2half2_rn(sacc[2 * kk][2],     sacc[2 * kk][3]));
            pH[2] = h2u(__floats2half2_rn(sacc[2 * kk + 1][0], sacc[2 * kk + 1][1]));
            pH[3] = h2u(__floats2half2_rn(sacc[2 * kk + 1][2], sacc[2 * kk + 1][3]));

            unsigned vHf[4][4];
            const unsigned slab = kvb + 16384 + (kk >> 1) * 4096;
            const unsigned koff = (kk & 1) * 32 + bkp;
#pragma unroll
            for (int p = 0; p < 4; p++) {
                unsigned sw = sw64((p * 16 + brow) * 64 + koff);
                LDSM4(vHf[p][0], vHf[p][1], vHf[p][2], vHf[p][3], slab + sw);
            }
#pragma unroll
            for (int j = 0; j < 8; j++) {
                const int p = j >> 1, h = (j & 1) * 2;
                MMA16816H(oacc[j], pH, vHf[p][h], vHf[p][h + 1]);
            }
        }

        __syncthreads();   // compute(ck) done before KV buf is re-prefetched
    }

    const float inv0 = 1.0f / l0r, inv1 = 1.0f / l1r;
    const int b = bh >> 3, h = bh & 7;
    const long row0 = (long)(b * SQ + qw + g) * EMB + h * HD;
    const long row1 = (long)(b * SQ + qw + g + 8) * EMB + h * HD;
#pragma unroll
    for (int j = 0; j < 8; j++) {
        int col = j * 8 + 2 * t;
        *reinterpret_cast<unsigned*>(&vals[row0 + col]) =
            h2u(__floats2half2_rn(oacc[j][0] * inv0, oacc[j][1] * inv0));
        *reinterpret_cast<unsigned*>(&vals[row1 + col]) =
            h2u(__floats2half2_rn(oacc[j][2] * inv1, oacc[j][3] * inv1));
    }
}

// ------------------------------ launch -------------------------------------
extern "C" void kernel_launch(void* const* d_in, const int* in_sizes, int n_in,
                              void* d_out, int out_size)
{
    const float* x    = (const float*)d_in[0];
    const float* PE   = (const float*)d_in[1];
    const float* PE_r = (const float*)d_in[2];
    const float* Wqkv = (const float*)d_in[3];
    const float* UqUk = (const float*)d_in[4];
    const float* Wo   = (const float*)d_in[5];
    float* out = (float*)d_out;

    void* p;
    cudaGetSymbolAddress(&p, g_x2);    unsigned short* x2  = (unsigned short*)p;
    cudaGetSymbolAddress(&p, g_PE2);   unsigned short* pe2 = (unsigned short*)p;
    cudaGetSymbolAddress(&p, g_W2);    unsigned short* w2  = (unsigned short*)p;
    cudaGetSymbolAddress(&p, g_U2);    unsigned short* u2  = (unsigned short*)p;
    cudaGetSymbolAddress(&p, g_Wo2);   unsigned short* wo2 = (unsigned short*)p;
    cudaGetSymbolAddress(&p, g_Qcat);  unsigned short* Qc  = (unsigned short*)p;
    cudaGetSymbolAddress(&p, g_KH);    char* KH = (char*)p;
    cudaGetSymbolAddress(&p, g_VH);    char* VH = (char*)p;
    cudaGetSymbolAddress(&p, g_vals);  unsigned short* Vl = (unsigned short*)p;

    // 0) pack activations + weights (PE_r consumed raw by flash)
    pack_all_kernel<<<9728, 256>>>((const float4*)x, (const float4*)PE,
                                   (const float4*)Wqkv, (const float4*)UqUk,
                                   (const float4*)Wo,
                                   (uint2*)x2, (uint2*)pe2,
                                   (uint2*)w2, (uint2*)u2, (uint2*)wo2);

    // 1) merged qkv + PE projections
    cudaFuncSetAttribute(proj_kernel, cudaFuncAttributeMaxDynamicSharedMemorySize, 67584);
    proj_kernel<<<dim3(20, 64), 256, 67584>>>(x2, w2, pe2, u2);

    // 2) fused attention (2 CTAs/SM, direct f32 bias)
    cudaFuncSetAttribute(flash_attn, cudaFuncAttributeMaxDynamicSharedMemorySize, 83968);
    flash_attn<<<dim3(SQ / 128, BB * HH), 256, 83968>>>(Qc, KH, VH, PE_r, Vl);

    // 3) out projection
    cudaFuncSetAttribute(outproj_kernel, cudaFuncAttributeMaxDynamicSharedMemorySize, 67584);
    outproj_kernel<<<dim3(4, 64), 256, 67584>>>(Vl, wo2, out);
}

// round 16
// speedup vs baseline: 1.0824x; 1.0824x over previous
#include <cuda_runtime.h>
#include <cuda_fp16.h>
#include <cstdint>

// ---------------------------------------------------------------------------
// TUPE multihead attention — plain fp16 HMMA (fp32 accumulate) everywhere.
//  Projections: 128x128x64 tile (sw128), cp.async double-buffered; qkv + PE
//  merged in one launch, PLUS bias-pack CTAs folded into the same grid
//  (memory-bound work overlaps tensor-bound tiles).
//  Flash: round-14 version (2 CTAs/SM, KV + fp16 bias double-buffered).
// ---------------------------------------------------------------------------

static constexpr int BB  = 4;
static constexpr int HH  = 8;
static constexpr int SQ  = 2048;
static constexpr int EMB = 512;
static constexpr int HD  = 64;
static constexpr float LOG2E = 1.4426950408889634f;
static constexpr float QK_SCALE_L2E = 0.0883883476483184f * LOG2E;

// ------------------------------ scratch ------------------------------------
__device__ __align__(16) unsigned short g_x2  [(size_t)BB * SQ * EMB];
__device__ __align__(16) unsigned short g_PE2 [(size_t)BB * SQ * EMB];
__device__ __align__(16) unsigned short g_W2  [(size_t)3 * EMB * EMB];
__device__ __align__(16) unsigned short g_U2  [(size_t)2 * EMB * EMB];
__device__ __align__(16) unsigned short g_Wo2 [(size_t)EMB * EMB];
__device__ __align__(16) unsigned short g_PEr16[(size_t)HH * SQ * SQ];      // fp16, x log2e
__device__ __align__(16) unsigned short g_Qcat[(size_t)BB * HH * SQ * 128]; // fp16 (x s*log2e)
__device__ __align__(16) unsigned short g_KH[(size_t)BB * HH * SQ * 128];   // K image sw64
__device__ __align__(16) unsigned short g_VH[(size_t)BB * HH * HD * SQ];    // V image sw64
__device__ __align__(16) unsigned short g_vals[(size_t)BB * SQ * EMB];

// ------------------------------ helpers ------------------------------------
__device__ __forceinline__ unsigned smem_u32(const void* p) {
    unsigned a;
    asm("{ .reg .u64 t; cvta.to.shared.u64 t, %1; cvt.u32.u64 %0, t; }" : "=r"(a) : "l"(p));
    return a;
}
__device__ __forceinline__ unsigned h2u(__half2 h) {
    return *reinterpret_cast<unsigned*>(&h);
}
__device__ __forceinline__ float ex2f(float x) {
    float r;
    asm("ex2.approx.f32 %0, %1;" : "=f"(r) : "f"(x));
    return r;
}

// merged pack: five f32 inputs -> fp16, segment dispatch by index
__global__ void __launch_bounds__(256)
pack_all_kernel(const float4* __restrict__ x,  const float4* __restrict__ pe,
                const float4* __restrict__ w,  const float4* __restrict__ u,
                const float4* __restrict__ wo,
                uint2* __restrict__ ox, uint2* __restrict__ ope,
                uint2* __restrict__ ow, uint2* __restrict__ ou,
                uint2* __restrict__ owo)
{
    const int N0 = 1048576, N1 = 2097152, N2 = 2293760, N3 = 2424832, N4 = 2490368;
    int i = blockIdx.x * 256 + threadIdx.x;
    if (i >= N4) return;
    const float4* src; uint2* dst; int j;
    if (i < N0)      { src = x;  dst = ox;  j = i; }
    else if (i < N1) { src = pe; dst = ope; j = i - N0; }
    else if (i < N2) { src = w;  dst = ow;  j = i - N1; }
    else if (i < N3) { src = u;  dst = ou;  j = i - N2; }
    else             { src = wo; dst = owo; j = i - N3; }
    float4 v = src[j];
    dst[j] = make_uint2(h2u(__floats2half2_rn(v.x, v.y)),
                        h2u(__floats2half2_rn(v.z, v.w)));
}

#define LDSM4(r0, r1, r2, r3, a)                                              \
    asm volatile("ldmatrix.sync.aligned.m8n8.x4.shared.b16 {%0,%1,%2,%3}, [%4];" \
                 : "=r"(r0), "=r"(r1), "=r"(r2), "=r"(r3) : "r"(a))

#define MMA16816H(c, a, b0, b1)                                               \
    asm volatile("mma.sync.aligned.m16n8k16.row.col.f32.f16.f16.f32 "         \
                 "{%0,%1,%2,%3}, {%4,%5,%6,%7}, {%8,%9}, {%0,%1,%2,%3};"      \
                 : "+f"((c)[0]), "+f"((c)[1]), "+f"((c)[2]), "+f"((c)[3])     \
                 : "r"((a)[0]), "r"((a)[1]), "r"((a)[2]), "r"((a)[3]),        \
                   "r"(b0), "r"(b1))

#define CP_ASYNC16(dst, src) \
    asm volatile("cp.async.cg.shared.global [%0], [%1], 16;" :: "r"(dst), "l"(src))
#define CP_COMMIT() asm volatile("cp.async.commit_group;" ::: "memory")
#define CP_WAIT0()  asm volatile("cp.async.wait_group 0;" ::: "memory")
#define CP_WAIT1()  asm volatile("cp.async.wait_group 1;" ::: "memory")

__device__ __forceinline__ unsigned sw64(unsigned off)   { return off ^ ((off >> 3) & 0x30); }
__device__ __forceinline__ unsigned sw128(unsigned off)  { return off ^ ((off >> 3) & 0x70); }

// ------------------------------ GEMM core (projections / out) --------------
// C[128 x 128]; A fp16 [M,K]; B fp16 [N,K]; K mult of 64. Warp tile 32x64.
template <typename Epi>
__device__ __forceinline__ void gemm_core(
    const unsigned short* __restrict__ Ab, const unsigned short* __restrict__ Bb,
    int K, int lda, int ldb, int bx, int by, int bz, Epi epi, char* smem)
{
    constexpr int SBOF = 16384, STAGE = 32768;
    const int tid = threadIdx.x;
    const int l   = tid & 31;
    const int w   = tid >> 5;
    const int m0  = (w & 3) * 32;
    const int n0  = (w >> 2) * 64;
    const unsigned sbase = smem_u32(smem);

    float acc[2][8][4];
#pragma unroll
    for (int i = 0; i < 2; i++)
#pragma unroll
        for (int j = 0; j < 8; j++)
#pragma unroll
            for (int k = 0; k < 4; k++) acc[i][j][k] = 0.0f;

    const int arow = (l & 7) + ((l >> 3) & 1) * 8;
    const int akp  = ((l >> 4) & 1) * 16;
    const int brow = (l & 7) + ((l >> 4) & 1) * 8;
    const int bkp  = ((l >> 3) & 1) * 16;

    const int nChunks = K >> 6;

    auto prefetch = [&](int c) {
        const unsigned sb = sbase + (c & 1) * STAGE;
#pragma unroll
        for (int it = 0; it < 4; it++) {
            int idx = tid + it * 256;
            int r = idx >> 3, q = idx & 7;
            CP_ASYNC16(sb + sw128(r * 128 + q * 16), Ab + (long)r * lda + c * 64 + q * 8);
        }
#pragma unroll
        for (int it = 0; it < 4; it++) {
            int idx = tid + it * 256;
            int r = idx >> 3, q = idx & 7;
            CP_ASYNC16(sb + SBOF + sw128(r * 128 + q * 16), Bb + (long)r * ldb + c * 64 + q * 8);
        }
    };

    prefetch(0);
    CP_COMMIT();

    for (int c = 0; c < nChunks; c++) {
        if (c + 1 < nChunks) {
            prefetch(c + 1);
            CP_COMMIT();
            CP_WAIT1();
        } else {
            CP_WAIT0();
        }
        __syncthreads();

        const unsigned stage = sbase + (c & 1) * STAGE;
#pragma unroll
        for (int ks = 0; ks < 4; ks++) {
            unsigned aH[2][4], bH[4][4];
#pragma unroll
            for (int i = 0; i < 2; i++) {
                unsigned off = (m0 + i * 16 + arow) * 128 + ks * 32 + akp;
                LDSM4(aH[i][0], aH[i][1], aH[i][2], aH[i][3], stage + sw128(off));
            }
#pragma unroll
            for (int p = 0; p < 4; p++) {
                unsigned off = (n0 + p * 16 + brow) * 128 + ks * 32 + bkp;
                LDSM4(bH[p][0], bH[p][1], bH[p][2], bH[p][3], stage + SBOF + sw128(off));
            }
#pragma unroll
            for (int i = 0; i < 2; i++)
#pragma unroll
                for (int j = 0; j < 8; j++) {
                    const int p = j >> 1, h = (j & 1) * 2;
                    MMA16816H(acc[i][j], aH[i], bH[p][h], bH[p][h + 1]);
                }
        }
        __syncthreads();
    }

    float* C = reinterpret_cast<float*>(smem);
#pragma unroll
    for (int i = 0; i < 2; i++)
#pragma unroll
        for (int j = 0; j < 8; j++) {
            int r0  = m0 + i * 16 + (l >> 2);
            int col = n0 + j * 8 + (l & 3) * 2;
            *reinterpret_cast<float2*>(C + r0 * 132 + col)       = make_float2(acc[i][j][0], acc[i][j][1]);
            *reinterpret_cast<float2*>(C + (r0 + 8) * 132 + col) = make_float2(acc[i][j][2], acc[i][j][3]);
        }
    __syncthreads();

    {
        int r = tid >> 1, seg = (tid & 1) << 6;
        int m  = by * 128 + r;
        int nb = bx * 128 + seg;
        const float* Crow = C + r * 132 + seg;
#pragma unroll
        for (int i = 0; i < 16; i++) {
            float4 v = *reinterpret_cast<const float4*>(Crow + i * 4);
            epi(bz, m, nb + i * 4, v);
        }
    }
}

// ------------------------------ epilogues ----------------------------------
struct EpiQKV {   // m in [0,8192), n in [0,1536)
    __device__ void operator()(int, int m, int n, float4 v) const {
        int b = m >> 11, s = m & (SQ - 1);
        int h = n / 192, r = n - h * 192;
        int bh = b * HH + h;
        if (r < HD) {
            long row = ((long)bh * SQ + s);
            *reinterpret_cast<uint2*>(&g_Qcat[row * 128 + r]) =
                make_uint2(h2u(__floats2half2_rn(v.x * QK_SCALE_L2E, v.y * QK_SCALE_L2E)),
                           h2u(__floats2half2_rn(v.z * QK_SCALE_L2E, v.w * QK_SCALE_L2E)));
        } else if (r < 2 * HD) {
            int d0 = r - HD;
            int ck = s >> 6, rr = s & 63;
            long base = ((long)bh * 32 + ck) * 16384;
            unsigned off = (unsigned)((d0 >> 5) * 4096) + sw64(rr * 64 + (d0 & 31) * 2);
            *reinterpret_cast<uint2*>(reinterpret_cast<char*>(g_KH) + base + off) =
                make_uint2(h2u(__floats2half2_rn(v.x, v.y)),
                           h2u(__floats2half2_rn(v.z, v.w)));
        } else {
            int d = r - 2 * HD;
            int ck = s >> 6, kc = s & 63;
            long base = ((long)bh * 32 + ck) * 8192 + (kc >> 5) * 4096;
            int kb = (kc & 31) * 2;
#pragma unroll
            for (int i = 0; i < 4; i++) {
                float val = (&v.x)[i];
                unsigned off2 = sw64((d + i) * 64 + kb);
                *reinterpret_cast<__half*>(reinterpret_cast<char*>(g_VH) + base + off2) =
                    __float2half(val);
            }
        }
    }
};
struct EpiPE {    // n in [0,1024)
    __device__ void operator()(int, int m, int n, float4 v) const {
        int b = m >> 11, s = m & (SQ - 1);
        int h = n >> 7, r = n & 127;
        int bh = b * HH + h;
        if (r < HD) {
            long row = ((long)bh * SQ + s);
            *reinterpret_cast<uint2*>(&g_Qcat[row * 128 + HD + r]) =
                make_uint2(h2u(__floats2half2_rn(v.x * QK_SCALE_L2E, v.y * QK_SCALE_L2E)),
                           h2u(__floats2half2_rn(v.z * QK_SCALE_L2E, v.w * QK_SCALE_L2E)));
        } else {
            int d0 = r;
            int ck = s >> 6, rr = s & 63;
            long base = ((long)bh * 32 + ck) * 16384;
            unsigned off = (unsigned)((d0 >> 5) * 4096) + sw64(rr * 64 + (d0 & 31) * 2);
            *reinterpret_cast<uint2*>(reinterpret_cast<char*>(g_KH) + base + off) =
                make_uint2(h2u(__floats2half2_rn(v.x, v.y)),
                           h2u(__floats2half2_rn(v.z, v.w)));
        }
    }
};
struct EpiOut {
    float* out;
    __device__ void operator()(int, int m, int n, float4 v) const {
        *reinterpret_cast<float4*>(&out[(long)m * EMB + n]) = v;
    }
};

// ------------------------------ merged projection + bias-pack kernel -------
// bx < 12 : qkv tile (A=x2, B=W2)
// bx < 20 : PE tile  (A=PE2, B=U2)
// bx >= 20: bias pack slice (PE_r f32 -> fp16 x log2e), 16 x 64 slices x 8192 f4
__global__ void __launch_bounds__(256, 2)
proj_kernel(const unsigned short* __restrict__ x2, const unsigned short* __restrict__ w2,
            const unsigned short* __restrict__ pe2, const unsigned short* __restrict__ u2,
            const float4* __restrict__ per, uint2* __restrict__ pr16)
{
    extern __shared__ __align__(1024) char smem[];
    const int bx = blockIdx.x, by = blockIdx.y;
    if (bx < 12) {
        gemm_core(x2 + (long)by * 128 * EMB, w2 + (long)bx * 128 * EMB,
                  EMB, EMB, EMB, bx, by, 0, EpiQKV{}, smem);
    } else if (bx < 20) {
        gemm_core(pe2 + (long)by * 128 * EMB, u2 + (long)(bx - 12) * 128 * EMB,
                  EMB, EMB, EMB, bx - 12, by, 0, EpiPE{}, smem);
    } else {
        long base = ((long)((bx - 20) + 16 * by)) * 8192 + threadIdx.x;
#pragma unroll
        for (int it = 0; it < 32; it++) {
            long i = base + it * 256;
            float4 v = per[i];
            pr16[i] = make_uint2(h2u(__floats2half2_rn(v.x * LOG2E, v.y * LOG2E)),
                                 h2u(__floats2half2_rn(v.z * LOG2E, v.w * LOG2E)));
        }
    }
}

__global__ void __launch_bounds__(256, 2)
outproj_kernel(const unsigned short* __restrict__ vals, const unsigned short* __restrict__ wo2,
               float* __restrict__ out)
{
    extern __shared__ __align__(1024) char smem[];
    gemm_core(vals + (long)blockIdx.y * 128 * EMB, wo2 + (long)blockIdx.x * 128 * EMB,
              EMB, EMB, EMB, blockIdx.x, blockIdx.y, 0, EpiOut{out}, smem);
}

// ------------------------------ flash attention (round 14) -----------------
// One CTA = 128 q-rows of one (b,h). 8 warps x 16 q-rows. KV chunk = 64 keys.
// 2 CTAs/SM: smem 86KB (KV x2 @0, fp16 bias x2 @49152), regs capped at 128.
__global__ void __launch_bounds__(256, 2)
flash_attn(const unsigned short* __restrict__ Qc, const char* __restrict__ KH,
           const char* __restrict__ VH, const char* __restrict__ PEr,
           unsigned short* __restrict__ vals)
{
    extern __shared__ __align__(1024) char smem[];
    constexpr int KVBUF = 24576;     // KH 16K | VH 8K
    constexpr int SBIAS = 49152, BIAS_STRIDE = 144, BIAS_BUF = 18432;
    constexpr int NCHUNK = SQ / 64;  // 32

    const int tid = threadIdx.x;
    const int l = tid & 31;
    const int w = tid >> 5;
    const int g = l >> 2;
    const int t = l & 3;
    const int bh = blockIdx.y;
    const int q0 = blockIdx.x * 128;
    const int qw = q0 + w * 16;
    const unsigned sbase = smem_u32(smem);

    const unsigned short* Qb = Qc + ((long)bh * SQ + qw) * 128;
    const char* KHb = KH + (long)bh * 32 * 16384;
    const char* VHb = VH + (long)bh * 32 * 8192;
    const char* Pb = PEr + (((long)(bh & 7) * SQ + q0) * SQ) * 2;

    unsigned qH[8][4];
#pragma unroll
    for (int kc = 0; kc < 8; kc++) {
        qH[kc][0] = *reinterpret_cast<const unsigned*>(Qb + (long)g * 128 + kc * 16 + 2 * t);
        qH[kc][1] = *reinterpret_cast<const unsigned*>(Qb + (long)(g + 8) * 128 + kc * 16 + 2 * t);
        qH[kc][2] = *reinterpret_cast<const unsigned*>(Qb + (long)g * 128 + kc * 16 + 8 + 2 * t);
        qH[kc][3] = *reinterpret_cast<const unsigned*>(Qb + (long)(g + 8) * 128 + kc * 16 + 8 + 2 * t);
    }

    float oacc[8][4];
#pragma unroll
    for (int j = 0; j < 8; j++)
#pragma unroll
        for (int k = 0; k < 4; k++) oacc[j][k] = 0.0f;
    float m0r = -1e30f, m1r = -1e30f, l0r = 0.0f, l1r = 0.0f;

    const int brow = (l & 7) + ((l >> 4) & 1) * 8;
    const int bkp  = ((l >> 3) & 1) * 16;

    auto prefetch = [&](int ck) {
        const int buf = ck & 1;
        const unsigned sb = sbase + buf * KVBUF;
        const char* kh = KHb + (long)ck * 16384;
        const char* vh = VHb + (long)ck * 8192;
#pragma unroll
        for (int it = 0; it < 4; it++) {
            int o = (tid + it * 256) * 16;
            CP_ASYNC16(sb + o, kh + o);
        }
#pragma unroll
        for (int it = 0; it < 2; it++) {
            int o = (tid + it * 256) * 16;
            CP_ASYNC16(sb + 16384 + o, vh + o);
        }
        const unsigned bb = sbase + SBIAS + buf * BIAS_BUF;
#pragma unroll
        for (int it = 0; it < 4; it++) {
            int idx = tid + it * 256;
            int r = idx >> 3, c = idx & 7;
            CP_ASYNC16(bb + r * BIAS_STRIDE + c * 16,
                       Pb + ((long)r * SQ + ck * 64 + c * 8) * 2);
        }
    };

    prefetch(0);
    CP_COMMIT();

    for (int ck = 0; ck < NCHUNK; ck++) {
        if (ck + 1 < NCHUNK) {
            prefetch(ck + 1);
            CP_COMMIT();
            CP_WAIT1();
        } else {
            CP_WAIT0();
        }
        __syncthreads();

        const int buf = ck & 1;
        const unsigned kvb = sbase + buf * KVBUF;

        float sacc[8][4];
#pragma unroll
        for (int j = 0; j < 8; j++)
#pragma unroll
            for (int k = 0; k < 4; k++) sacc[j][k] = 0.0f;

#pragma unroll
        for (int kc = 0; kc < 8; kc++) {
            unsigned bH[4][4];
            const unsigned slab = kvb + (kc >> 1) * 4096;
            const unsigned koff = (kc & 1) * 32 + bkp;
#pragma unroll
            for (int p = 0; p < 4; p++) {
                unsigned sw = sw64((p * 16 + brow) * 64 + koff);
                LDSM4(bH[p][0], bH[p][1], bH[p][2], bH[p][3], slab + sw);
            }
#pragma unroll
            for (int j = 0; j < 8; j++) {
                const int p = j >> 1, h = (j & 1) * 2;
                MMA16816H(sacc[j], qH[kc], bH[p][h], bH[p][h + 1]);
            }
        }

        {
            const char* bb = smem + SBIAS + buf * BIAS_BUF;
            const int r0 = w * 16 + g, r1 = r0 + 8;
#pragma unroll
            for (int j = 0; j < 8; j++) {
                float2 b0 = __half22float2(*reinterpret_cast<const __half2*>(
                    bb + r0 * BIAS_STRIDE + (j * 8 + 2 * t) * 2));
                float2 b1 = __half22float2(*reinterpret_cast<const __half2*>(
                    bb + r1 * BIAS_STRIDE + (j * 8 + 2 * t) * 2));
                sacc[j][0] += b0.x; sacc[j][1] += b0.y;
                sacc[j][2] += b1.x; sacc[j][3] += b1.y;
            }
        }

        float mx0 = -1e30f, mx1 = -1e30f;
#pragma unroll
        for (int j = 0; j < 8; j++) {
            mx0 = fmaxf(mx0, fmaxf(sacc[j][0], sacc[j][1]));
            mx1 = fmaxf(mx1, fmaxf(sacc[j][2], sacc[j][3]));
        }
        mx0 = fmaxf(mx0, __shfl_xor_sync(0xffffffffu, mx0, 1));
        mx0 = fmaxf(mx0, __shfl_xor_sync(0xffffffffu, mx0, 2));
        mx1 = fmaxf(mx1, __shfl_xor_sync(0xffffffffu, mx1, 1));
        mx1 = fmaxf(mx1, __shfl_xor_sync(0xffffffffu, mx1, 2));

        const float mn0 = fmaxf(m0r, mx0), mn1 = fmaxf(m1r, mx1);
        const float cor0 = ex2f(m0r - mn0), cor1 = ex2f(m1r - mn1);
        m0r = mn0; m1r = mn1;

        float sum0 = 0.0f, sum1 = 0.0f;
#pragma unroll
        for (int j = 0; j < 8; j++) {
            sacc[j][0] = ex2f(sacc[j][0] - mn0);
            sacc[j][1] = ex2f(sacc[j][1] - mn0);
            sacc[j][2] = ex2f(sacc[j][2] - mn1);
            sacc[j][3] = ex2f(sacc[j][3] - mn1);
            sum0 += sacc[j][0] + sacc[j][1];
            sum1 += sacc[j][2] + sacc[j][3];
        }
        sum0 += __shfl_xor_sync(0xffffffffu, sum0, 1);
        sum0 += __shfl_xor_sync(0xffffffffu, sum0, 2);
        sum1 += __shfl_xor_sync(0xffffffffu, sum1, 1);
        sum1 += __shfl_xor_sync(0xffffffffu, sum1, 2);
        l0r = l0r * cor0 + sum0;
        l1r = l1r * cor1 + sum1;

#pragma unroll
        for (int j = 0; j < 8; j++) {
            oacc[j][0] *= cor0; oacc[j][1] *= cor0;
            oacc[j][2] *= cor1; oacc[j][3] *= cor1;
        }

#pragma unroll
        for (int kk = 0; kk < 4; kk++) {
            unsigned pH[4];
            pH[0] = h2u(__floats2half2_rn(sacc[2 * kk][0],     sacc[2 * kk][1]));
            pH[1] = h2u(__floats2half2_rn(sacc[2 * kk][2],     sacc[2 * kk][3]));
            pH[2] = h2u(__floats2half2_rn(sacc[2 * kk + 1][0], sacc[2 * kk + 1][1]));
            pH[3] = h2u(__floats2half2_rn(sacc[2 * kk + 1][2], sacc[2 * kk + 1][3]));

            unsigned vHf[4][4];
            const unsigned slab = kvb + 16384 + (kk >> 1) * 4096;
            const unsigned koff = (kk & 1) * 32 + bkp;
#pragma unroll
            for (int p = 0; p < 4; p++) {
                unsigned sw = sw64((p * 16 + brow) * 64 + koff);
                LDSM4(vHf[p][0], vHf[p][1], vHf[p][2], vHf[p][3], slab + sw);
            }
#pragma unroll
            for (int j = 0; j < 8; j++) {
                const int p = j >> 1, h = (j & 1) * 2;
                MMA16816H(oacc[j], pH, vHf[p][h], vHf[p][h + 1]);
            }
        }

        __syncthreads();
    }

    const float inv0 = 1.0f / l0r, inv1 = 1.0f / l1r;
    const int b = bh >> 3, h = bh & 7;
    const long row0 = (long)(b * SQ + qw + g) * EMB + h * HD;
    const long row1 = (long)(b * SQ + qw + g + 8) * EMB + h * HD;
#pragma unroll
    for (int j = 0; j < 8; j++) {
        int col = j * 8 + 2 * t;
        *reinterpret_cast<unsigned*>(&vals[row0 + col]) =
            h2u(__floats2half2_rn(oacc[j][0] * inv0, oacc[j][1] * inv0));
        *reinterpret_cast<unsigned*>(&vals[row1 + col]) =
            h2u(__floats2half2_rn(oacc[j][2] * inv1, oacc[j][3] * inv1));
    }
}

// ------------------------------ launch -------------------------------------
extern "C" void kernel_launch(void* const* d_in, const int* in_sizes, int n_in,
                              void* d_out, int out_size)
{
    const float* x    = (const float*)d_in[0];
    const float* PE   = (const float*)d_in[1];
    const float* PE_r = (const float*)d_in[2];
    const float* Wqkv = (const float*)d_in[3];
    const float* UqUk = (const float*)d_in[4];
    const float* Wo   = (const float*)d_in[5];
    float* out = (float*)d_out;

    void* p;
    cudaGetSymbolAddress(&p, g_x2);    unsigned short* x2  = (unsigned short*)p;
    cudaGetSymbolAddress(&p, g_PE2);   unsigned short* pe2 = (unsigned short*)p;
    cudaGetSymbolAddress(&p, g_W2);    unsigned short* w2  = (unsigned short*)p;
    cudaGetSymbolAddress(&p, g_U2);    unsigned short* u2  = (unsigned short*)p;
    cudaGetSymbolAddress(&p, g_Wo2);   unsigned short* wo2 = (unsigned short*)p;
    cudaGetSymbolAddress(&p, g_PEr16); unsigned short* pr16 = (unsigned short*)p;
    cudaGetSymbolAddress(&p, g_Qcat);  unsigned short* Qc  = (unsigned short*)p;
    cudaGetSymbolAddress(&p, g_KH);    char* KH = (char*)p;
    cudaGetSymbolAddress(&p, g_VH);    char* VH = (char*)p;
    cudaGetSymbolAddress(&p, g_vals);  unsigned short* Vl = (unsigned short*)p;

    // 0) pack activations + weights
    pack_all_kernel<<<9728, 256>>>((const float4*)x, (const float4*)PE,
                                   (const float4*)Wqkv, (const float4*)UqUk,
                                   (const float4*)Wo,
                                   (uint2*)x2, (uint2*)pe2,
                                   (uint2*)w2, (uint2*)u2, (uint2*)wo2);

    // 1) merged qkv + PE projections + bias pack (overlapped)
    cudaFuncSetAttribute(proj_kernel, cudaFuncAttributeMaxDynamicSharedMemorySize, 67584);
    proj_kernel<<<dim3(36, 64), 256, 67584>>>(x2, w2, pe2, u2,
                                              (const float4*)PE_r, (uint2*)pr16);

    // 2) fused attention (2 CTAs/SM, fp16 bias double-buffered)
    cudaFuncSetAttribute(flash_attn, cudaFuncAttributeMaxDynamicSharedMemorySize, 86016);
    flash_attn<<<dim3(SQ / 128, BB * HH), 256, 86016>>>(Qc, KH, VH, (const char*)pr16, Vl);

    // 3) out projection
    cudaFuncSetAttribute(outproj_kernel, cudaFuncAttributeMaxDynamicSharedMemorySize, 67584);
    outproj_kernel<<<dim3(4, 64), 256, 67584>>>(Vl, wo2, out);
}